// round 1
// baseline (speedup 1.0000x reference)
#include <cuda_runtime.h>

#define B_TOT 16384
#define NNODE 33
#define KN 32
#define D 64
#define ED 16
#define ROWSTRIDE 68   // floats per node row in smem (16B aligned, conflict-tuned)
#define EPSLN 1e-5f

typedef unsigned long long ull;

// Precomputed on device each call (deterministic, graph-capturable)
__device__ __align__(16) ull   g_Wt2s[64 * 32];  // transposed, i-paired, xor-swizzled W
__device__ __align__(16) float g_wproj[64];      // W_w @ attn_w[64:128]
__device__ __align__(16) float g_ewproj[16];     // We_w @ attn_w[128:192]

__device__ __forceinline__ float f2lo(ull v) { return __uint_as_float((unsigned)v); }
__device__ __forceinline__ float f2hi(ull v) { return __uint_as_float((unsigned)(v >> 32)); }
__device__ __forceinline__ ull packf2(float lo, float hi) {
    return ((ull)__float_as_uint(hi) << 32) | (ull)__float_as_uint(lo);
}

// Packed dual-fp32 FMA (Blackwell f32x2 pipe): d = a*b + d elementwise on 2 lanes
#define FFMA2(d, a, b) asm("fma.rn.f32x2 %0, %1, %2, %0;" : "+l"(d) : "l"(a), "l"(b))

__global__ void prep_kernel(const float* __restrict__ Ww,
                            const float* __restrict__ Wew,
                            const float* __restrict__ attw) {
    int t = threadIdx.x;  // 64 threads
    // wproj[i] = sum_o W_w[i][o] * attn_w[64+o]
    float s = 0.f;
#pragma unroll 8
    for (int o = 0; o < 64; ++o) s += Ww[t * 64 + o] * attw[64 + o];
    g_wproj[t] = s;
    if (t < 16) {
        float se = 0.f;
#pragma unroll 8
        for (int o = 0; o < 64; ++o) se += Wew[t * 64 + o] * attw[128 + o];
        g_ewproj[t] = se;
    }
    // Wt2s[o][i2 ^ (o&31)] = (W[2*i2][o], W[2*i2+1][o])  -- conflict-free LDS.64 reads
    for (int i2 = 0; i2 < 32; ++i2) {
        g_Wt2s[t * 32 + (i2 ^ (t & 31))] =
            packf2(Ww[(2 * i2) * 64 + t], Ww[(2 * i2 + 1) * 64 + t]);
    }
}

__global__ __launch_bounds__(256) void gat_kernel(
    const float* __restrict__ nodes,
    const float* __restrict__ edges,
    const float* __restrict__ Wb,
    const float* __restrict__ gamma,
    const float* __restrict__ beta,
    float* __restrict__ out)
{
    __shared__ ull   sW[64 * 32];                 // 16 KB, shared by both batches
    __shared__ float sN[2][NNODE * ROWSTRIDE];    // staged nodes per batch
    __shared__ float sAttn[2][KN];
    __shared__ float sMsg[2][4][64];

    const int tid  = threadIdx.x;
    const int lane = tid & 31;
    const int bl   = tid >> 7;          // which of 2 batches in this CTA
    const int w4   = (tid >> 5) & 3;    // warp within batch (4 warps/batch)
    const long long b = (long long)blockIdx.x * 2 + bl;

    // ---- stage swizzled W (all threads) ----
#pragma unroll
    for (int t = tid; t < 64 * 32; t += 256) sW[t] = g_Wt2s[t];

    // ---- stage nodes for this batch (128 threads per batch) ----
    const float* gN = nodes + b * (NNODE * D);
    const int lt = tid & 127;
    for (int q = lt; q < NNODE * D / 4; q += 128) {
        int n  = q >> 4;
        int i4 = q & 15;
        float4 v = ((const float4*)gN)[q];
        *(float4*)&sN[bl][n * ROWSTRIDE + i4 * 4] = v;
    }

    // ---- attention scores + softmax (warp 0 of each batch, straight from gmem) ----
    // Softmax shift-invariance cancels every k-constant term, so:
    //   s_k = nodes[k+1] . wproj + edge_k . ewproj
    if (w4 == 0) {
        const int k = lane;
        const float4* nrow = (const float4*)(gN + (k + 1) * D);
        float s = 0.f;
#pragma unroll
        for (int i4 = 0; i4 < 16; ++i4) {
            float4 a = nrow[i4];
            float4 w = *(const float4*)&g_wproj[i4 * 4];
            s += a.x * w.x + a.y * w.y + a.z * w.z + a.w * w.w;
        }
        const float4* erow = (const float4*)(edges + (b * KN + k) * ED);
#pragma unroll
        for (int e4 = 0; e4 < 4; ++e4) {
            float4 a = erow[e4];
            float4 w = *(const float4*)&g_ewproj[e4 * 4];
            s += a.x * w.x + a.y * w.y + a.z * w.z + a.w * w.w;
        }
        float m = s;
#pragma unroll
        for (int d = 16; d > 0; d >>= 1) m = fmaxf(m, __shfl_xor_sync(0xffffffffu, m, d));
        float p = __expf(s - m);
        float tot = p;
#pragma unroll
        for (int d = 16; d > 0; d >>= 1) tot += __shfl_xor_sync(0xffffffffu, tot, d);
        sAttn[bl][k] = p / tot;
    }
    __syncthreads();

    // ---- GEMM: h = nodes @ W  via packed f32x2 FMAs ----
    // warp tile: 9 rows (8/6 at tail) x 64 cols (lane -> o=lane and o=lane+32)
    const int rowBase = w4 * 9;
    const int nrows   = (w4 == 3) ? 6 : 9;
    ull acc[9][2];
#pragma unroll
    for (int j = 0; j < 9; ++j) { acc[j][0] = 0ull; acc[j][1] = 0ull; }

    const ull* w0p = sW + lane * 32;
    const ull* w1p = sW + (lane + 32) * 32;
    const float* nb = sN[bl] + rowBase * ROWSTRIDE;

#pragma unroll 4
    for (int i2 = 0; i2 < 32; i2 += 2) {
        ull w00 = w0p[i2 ^ lane];
        ull w01 = w0p[(i2 + 1) ^ lane];
        ull w10 = w1p[i2 ^ lane];
        ull w11 = w1p[(i2 + 1) ^ lane];
#pragma unroll
        for (int j = 0; j < 9; ++j) {
            if (j < nrows) {
                ulonglong2 a = *(const ulonglong2*)(nb + j * ROWSTRIDE + 2 * i2);
                FFMA2(acc[j][0], a.x, w00);
                FFMA2(acc[j][0], a.y, w01);
                FFMA2(acc[j][1], a.x, w10);
                FFMA2(acc[j][1], a.y, w11);
            }
        }
    }

    // ---- epilogue: h, message partials, layernorm ----
    const float wb0 = Wb[lane],       wb1 = Wb[lane + 32];
    const float g0  = gamma[lane],    g1  = gamma[lane + 32];
    const float be0 = beta[lane],     be1 = beta[lane + 32];
    float* gO = out + b * (NNODE * D);

    float pm0 = 0.f, pm1 = 0.f;
    float t00 = 0.f, t01 = 0.f;  // row-0 h values (only valid on w4==0)

#pragma unroll
    for (int j = 0; j < 9; ++j) {
        if (j < nrows) {
            int row = rowBase + j;
            float h0 = f2lo(acc[j][0]) + f2hi(acc[j][0]) + wb0;
            float h1 = f2lo(acc[j][1]) + f2hi(acc[j][1]) + wb1;
            if (row == 0) {
                t00 = h0; t01 = h1;
            } else {
                float a = sAttn[bl][row - 1];
                pm0 = fmaf(a, h0, pm0);
                pm1 = fmaf(a, h1, pm1);
                // layernorm rows 1..32 (independent of message)
                float s  = h0 + h1;
                float s2 = fmaf(h0, h0, h1 * h1);
#pragma unroll
                for (int d = 16; d > 0; d >>= 1) {
                    s  += __shfl_xor_sync(0xffffffffu, s,  d);
                    s2 += __shfl_xor_sync(0xffffffffu, s2, d);
                }
                float mu  = s * (1.f / 64.f);
                float var = fmaf(s2, 1.f / 64.f, -mu * mu);
                float r   = rsqrtf(var + EPSLN);
                gO[row * D + lane]      = fmaf((h0 - mu) * r, g0, be0);
                gO[row * D + lane + 32] = fmaf((h1 - mu) * r, g1, be1);
            }
        }
    }
    sMsg[bl][w4][lane]      = pm0;
    sMsg[bl][w4][lane + 32] = pm1;
    __syncthreads();

    // row 0: target + aggregated message, then layernorm
    if (w4 == 0) {
        float m0 = (sMsg[bl][0][lane] + sMsg[bl][1][lane]) +
                   (sMsg[bl][2][lane] + sMsg[bl][3][lane]);
        float m1 = (sMsg[bl][0][lane + 32] + sMsg[bl][1][lane + 32]) +
                   (sMsg[bl][2][lane + 32] + sMsg[bl][3][lane + 32]);
        float h0 = t00 + m0;
        float h1 = t01 + m1;
        float s  = h0 + h1;
        float s2 = fmaf(h0, h0, h1 * h1);
#pragma unroll
        for (int d = 16; d > 0; d >>= 1) {
            s  += __shfl_xor_sync(0xffffffffu, s,  d);
            s2 += __shfl_xor_sync(0xffffffffu, s2, d);
        }
        float mu  = s * (1.f / 64.f);
        float var = fmaf(s2, 1.f / 64.f, -mu * mu);
        float r   = rsqrtf(var + EPSLN);
        gO[lane]      = fmaf((h0 - mu) * r, g0, be0);
        gO[lane + 32] = fmaf((h1 - mu) * r, g1, be1);
    }
}

extern "C" void kernel_launch(void* const* d_in, const int* in_sizes, int n_in,
                              void* d_out, int out_size) {
    const float* nodes = (const float*)d_in[0];
    const float* edges = (const float*)d_in[1];
    const float* Ww    = (const float*)d_in[2];
    const float* Wb    = (const float*)d_in[3];
    const float* Wew   = (const float*)d_in[4];
    // d_in[5] = We_b  (cancels in softmax)
    const float* attw  = (const float*)d_in[6];
    // d_in[7] = attn_b (cancels in softmax)
    const float* gamma = (const float*)d_in[8];
    const float* beta  = (const float*)d_in[9];

    prep_kernel<<<1, 64>>>(Ww, Wew, attw);
    gat_kernel<<<B_TOT / 2, 256>>>(nodes, edges, Wb, gamma, beta, (float*)d_out);
}